// round 2
// baseline (speedup 1.0000x reference)
#include <cuda_runtime.h>
#include <cstdint>

#define BATCH 512
#define TSEQ  64
#define P_DIM 8
#define Q_DIM 24
#define N_DIM 32
#define PQ    (P_DIM * Q_DIM)   // 192
#define CPAD  36                 // padded column stride for 32-row panels

// Scratch (no cudaMalloc allowed)
__device__ float g_yb[N_DIM * N_DIM];            // bias Cayley rotation, 32x32
__device__ float g_U[2 * BATCH * N_DIM * P_DIM]; // 1024 x (32x8) panels

// ---------------------------------------------------------------------------
// Kernel 1: yb = cayley(tangent(question_bias)). Single warp, syncwarp only.
// Real 8x8 Gauss-Jordan (SPD I + b b^T, pivots >= 1, no pivoting needed).
// ---------------------------------------------------------------------------
__global__ __launch_bounds__(32) void yb_kernel(const float* __restrict__ bias)
{
    __shared__ float sb[PQ];      // b, 8x24 row-major
    __shared__ float sA[8 * 16];  // augmented [I + b b^T | I]
    __shared__ float sW[PQ];      // W = K b

    const int tid = threadIdx.x;  // 0..31

    #pragma unroll
    for (int m = 0; m < 6; ++m) sb[tid + 32 * m] = bias[tid + 32 * m];
    __syncwarp();

    // A = [I + b b^T | I], each thread owns 4 entries (i = tid>>2, c0 = (tid&3)*4)
    {
        int i = tid >> 2, c0 = (tid & 3) * 4;
        #pragma unroll
        for (int cc = 0; cc < 4; ++cc) {
            int c = c0 + cc;
            float v;
            if (c < 8) {
                v = (i == c) ? 1.0f : 0.0f;
                #pragma unroll
                for (int k = 0; k < Q_DIM; ++k) v += sb[i * Q_DIM + k] * sb[c * Q_DIM + k];
            } else {
                v = (i == c - 8) ? 1.0f : 0.0f;
            }
            sA[i * 16 + c] = v;
        }
    }
    __syncwarp();

    // Gauss-Jordan, 8 pivots
    for (int k = 0; k < 8; ++k) {
        float piv = 1.0f / sA[k * 16 + k];
        int i = tid >> 2, c0 = (tid & 3) * 4;
        float nv[4];
        #pragma unroll
        for (int cc = 0; cc < 4; ++cc) {
            int c = c0 + cc;
            float akc = sA[k * 16 + c] * piv;
            float aik = sA[i * 16 + k];
            nv[cc] = (i == k) ? akc : (sA[i * 16 + c] - aik * akc);
        }
        __syncwarp();
        #pragma unroll
        for (int cc = 0; cc < 4; ++cc) sA[i * 16 + c0 + cc] = nv[cc];
        __syncwarp();
    }

    // W = K b  (K = right half of sA)
    #pragma unroll
    for (int m = 0; m < 6; ++m) {
        int idx = tid + 32 * m;
        int i = idx / Q_DIM, j = idx % Q_DIM;
        float w = 0.0f;
        #pragma unroll
        for (int k = 0; k < 8; ++k) w += sA[i * 16 + 8 + k] * sb[k * Q_DIM + j];
        sW[idx] = w;
    }
    __syncwarp();

    // Y = [[2K - I, -2W], [2W^T, I - 2 b^T W]]
    #pragma unroll
    for (int e = 0; e < 32; ++e) {
        int idx = tid + 32 * e;
        int r = idx >> 5, c = idx & 31;
        float y;
        if (r < 8 && c < 8) {
            y = 2.0f * sA[r * 16 + 8 + c] - ((r == c) ? 1.0f : 0.0f);
        } else if (r < 8) {
            y = -2.0f * sW[r * Q_DIM + (c - 8)];
        } else if (c < 8) {
            y = 2.0f * sW[c * Q_DIM + (r - 8)];
        } else {
            int j = r - 8, cc = c - 8;
            float acc = 0.0f;
            #pragma unroll
            for (int i = 0; i < 8; ++i) acc += sb[i * Q_DIM + j] * sW[i * Q_DIM + cc];
            y = ((j == cc) ? 1.0f : 0.0f) - 2.0f * acc;
        }
        g_yb[idx] = y;
    }
}

// ---------------------------------------------------------------------------
// Kernel 2: per-sequence chain, one block per (batch, q/a).
// C (32x8 panel) <- Y_t C via Horner:  E = XC - C; D = XE + C; C' = C - 2XD
// with X = [[0, x],[-x^T, 0]]  (error 2||X||^4 ~ 1e-8 per step).
// Panel stored column-major with pad: s?[c*CPAD + r].
// ---------------------------------------------------------------------------
__global__ __launch_bounds__(256) void seq_kernel(
    const int*   __restrict__ sent_q,
    const int*   __restrict__ sent_a,
    const float* __restrict__ emb_q,
    const float* __restrict__ emb_a,
    const float* __restrict__ transforms)
{
    const int bid   = blockIdx.x;
    const bool is_q = (bid < BATCH);
    const int b     = is_q ? bid : (bid - BATCH);
    const int* sent   = is_q ? sent_q : sent_a;
    const float* emb  = is_q ? emb_q  : emb_a;
    const int tid = threadIdx.x;
    const int r = tid >> 3, c = tid & 7;
    const bool top = (r < 8);
    const int j = r - 8;

    __shared__ float sx[2][PQ];       // double-buffered x, row-major 8x24
    __shared__ float sC[8 * CPAD];
    __shared__ float sE[8 * CPAD];
    __shared__ float sD[8 * CPAD];
    __shared__ int   stok[TSEQ];

    float tf = 1.0f;
    if (is_q && tid < PQ) tf = transforms[tid];
    if (tid < TSEQ) stok[tid] = sent[b * TSEQ + tid];
    sC[c * CPAD + r] = (r == c) ? 1.0f : 0.0f;
    __syncthreads();

    if (tid < PQ) sx[1][tid] = emb[(size_t)stok[TSEQ - 1] * PQ + tid] * tf;
    __syncthreads();

    float rx[24];   // top: x row r (24); bottom: x column j (8)

    for (int t = TSEQ - 1; t >= 0; --t) {
        const float* xb = sx[t & 1];

        // prefetch next token's embedding row into registers (L2-resident)
        float xn = 0.0f;
        if (t > 0 && tid < PQ) xn = emb[(size_t)stok[t - 1] * PQ + tid];

        // cache x slice in registers
        if (top) {
            const float4* px = (const float4*)(xb + r * Q_DIM);
            #pragma unroll
            for (int m = 0; m < 6; ++m) {
                float4 v = px[m];
                rx[4 * m] = v.x; rx[4 * m + 1] = v.y; rx[4 * m + 2] = v.z; rx[4 * m + 3] = v.w;
            }
        } else {
            #pragma unroll
            for (int i = 0; i < 8; ++i) rx[i] = xb[i * Q_DIM + j];
        }

        // ---- Phase 1: E = X C - C
        float acc;
        if (top) {
            acc = -sC[c * CPAD + r];
            const float4* pc = (const float4*)(&sC[c * CPAD + 8]);
            #pragma unroll
            for (int m = 0; m < 6; ++m) {
                float4 v = pc[m];
                acc += rx[4 * m] * v.x + rx[4 * m + 1] * v.y + rx[4 * m + 2] * v.z + rx[4 * m + 3] * v.w;
            }
        } else {
            acc = -sC[c * CPAD + r];
            const float4* pc = (const float4*)(&sC[c * CPAD]);
            float4 v0 = pc[0], v1 = pc[1];
            acc -= rx[0] * v0.x + rx[1] * v0.y + rx[2] * v0.z + rx[3] * v0.w
                 + rx[4] * v1.x + rx[5] * v1.y + rx[6] * v1.z + rx[7] * v1.w;
        }
        sE[c * CPAD + r] = acc;
        __syncthreads();

        // ---- Phase 2: D = X E + C
        if (top) {
            acc = sC[c * CPAD + r];
            const float4* pe = (const float4*)(&sE[c * CPAD + 8]);
            #pragma unroll
            for (int m = 0; m < 6; ++m) {
                float4 v = pe[m];
                acc += rx[4 * m] * v.x + rx[4 * m + 1] * v.y + rx[4 * m + 2] * v.z + rx[4 * m + 3] * v.w;
            }
        } else {
            acc = sC[c * CPAD + r];
            const float4* pe = (const float4*)(&sE[c * CPAD]);
            float4 v0 = pe[0], v1 = pe[1];
            acc -= rx[0] * v0.x + rx[1] * v0.y + rx[2] * v0.z + rx[3] * v0.w
                 + rx[4] * v1.x + rx[5] * v1.y + rx[6] * v1.z + rx[7] * v1.w;
        }
        sD[c * CPAD + r] = acc;
        __syncthreads();

        // ---- Phase 3 (in place): C1 -= 2 x D2 ; C2 += 2 x^T D1
        if (top) {
            acc = 0.0f;
            const float4* pd = (const float4*)(&sD[c * CPAD + 8]);
            #pragma unroll
            for (int m = 0; m < 6; ++m) {
                float4 v = pd[m];
                acc += rx[4 * m] * v.x + rx[4 * m + 1] * v.y + rx[4 * m + 2] * v.z + rx[4 * m + 3] * v.w;
            }
            sC[c * CPAD + r] -= 2.0f * acc;
        } else {
            acc = 0.0f;
            const float4* pd = (const float4*)(&sD[c * CPAD]);
            float4 v0 = pd[0], v1 = pd[1];
            acc += rx[0] * v0.x + rx[1] * v0.y + rx[2] * v0.z + rx[3] * v0.w
                 + rx[4] * v1.x + rx[5] * v1.y + rx[6] * v1.z + rx[7] * v1.w;
            sC[c * CPAD + r] += 2.0f * acc;
        }

        // commit next x (other buffer — no hazard with this step's readers)
        if (t > 0 && tid < PQ) sx[(t & 1) ^ 1][tid] = xn * tf;
        __syncthreads();
    }

    // Epilogue: question panel gets the bias rotation; answer panel raw.
    float u;
    if (is_q) {
        float acc = 0.0f;
        #pragma unroll
        for (int k = 0; k < N_DIM; ++k) acc += g_yb[r * N_DIM + k] * sC[c * CPAD + k];
        u = acc;
    } else {
        u = sC[c * CPAD + r];
    }
    g_U[(size_t)bid * (N_DIM * P_DIM) + r * P_DIM + c] = u;
}

// ---------------------------------------------------------------------------
// Kernel 3: dist_b = || U1 U1^T - U2 U2^T ||_F ; out = -wf*dist + wb
// ---------------------------------------------------------------------------
__global__ __launch_bounds__(256) void dist_kernel(
    const float* __restrict__ wf,
    const float* __restrict__ wb,
    float* __restrict__ out)
{
    const int b = blockIdx.x;
    const int tid = threadIdx.x;
    __shared__ float U1[N_DIM * 8];
    __shared__ float U2[N_DIM * 8];
    __shared__ float warpsum[8];

    U1[tid] = g_U[(size_t)b * 256 + tid];
    U2[tid] = g_U[(size_t)(BATCH + b) * 256 + tid];
    __syncthreads();

    float acc = 0.0f;
    #pragma unroll
    for (int e = 0; e < 4; ++e) {
        int idx = tid + 256 * e;
        int i = idx >> 5, jj = idx & 31;
        float d = 0.0f;
        #pragma unroll
        for (int c = 0; c < 8; ++c)
            d += U1[i * 8 + c] * U1[jj * 8 + c] - U2[i * 8 + c] * U2[jj * 8 + c];
        acc += d * d;
    }

    #pragma unroll
    for (int off = 16; off > 0; off >>= 1)
        acc += __shfl_xor_sync(0xFFFFFFFFu, acc, off);
    if ((tid & 31) == 0) warpsum[tid >> 5] = acc;
    __syncthreads();
    if (tid == 0) {
        float s = 0.0f;
        #pragma unroll
        for (int w = 0; w < 8; ++w) s += warpsum[w];
        out[b] = -(*wf) * sqrtf(s) + (*wb);
    }
}

// ---------------------------------------------------------------------------
extern "C" void kernel_launch(void* const* d_in, const int* in_sizes, int n_in,
                              void* d_out, int out_size)
{
    const int*   s1 = (const int*)  d_in[0];   // sentence_1 [512,64]
    const int*   s2 = (const int*)  d_in[1];   // sentence_2 [512,64]
    const float* qe = (const float*)d_in[2];   // question_embedding [32000,8,24]
    const float* ae = (const float*)d_in[3];   // answer_embedding   [32000,8,24]
    const float* qt = (const float*)d_in[4];   // question_transforms [8,24]
    const float* qb = (const float*)d_in[5];   // question_bias [8,24]
    const float* wf = (const float*)d_in[6];
    const float* wb = (const float*)d_in[7];
    float* out = (float*)d_out;

    yb_kernel<<<1, 32>>>(qb);
    seq_kernel<<<2 * BATCH, 256>>>(s1, s2, qe, ae, qt);
    dist_kernel<<<BATCH, 256>>>(wf, wb, out);
}

// round 3
// speedup vs baseline: 2.0568x; 2.0568x over previous
#include <cuda_runtime.h>
#include <cstdint>

#define BATCH 512
#define TSEQ  64
#define P_DIM 8
#define Q_DIM 24
#define N_DIM 32
#define PQ    (P_DIM * Q_DIM)   // 192
#define CPAD  36                // padded column stride (words) for 32-row panels
#define RPAD  12                // padded row stride for row-major 32x8 panels

// ---------------------------------------------------------------------------
// Single fused kernel. Block b handles question-seq b AND answer-seq b.
//
// Panel recurrence (exact to O(||X||^4) ~ 1e-10):
//   C <- Y_t C,  Y = I - 2X + 2X^2 - 2X^3  via Horner:
//   E = XC - C;  D = XE + C;  C' = C - 2XD
// with X = [[0, x],[-x^T, 0]],  x = 8x24.
//
// Thread layout (256 threads):
//   tid <  128 : question panel (p=0);  tid >= 128 : answer panel (p=1)
//   tp = tid & 127
//   tp <  64  (warps 0,1 / 4,5): "top"    — owns entry (r=tp>>3, c=tp&7); 24 FMA/phase
//   tp >= 64  (warps 2,3 / 6,7): "bottom" — owns rows 8+3*jg+{0,1,2}, col c
//              (jg=(tp-64)>>3, c=tp&7); 3x8 = 24 FMA/phase
// ---------------------------------------------------------------------------
__global__ __launch_bounds__(256) void fused_kernel(
    const int*   __restrict__ s1,
    const int*   __restrict__ s2,
    const float* __restrict__ emb_q,
    const float* __restrict__ emb_a,
    const float* __restrict__ transforms,
    const float* __restrict__ bias,
    const float* __restrict__ wf,
    const float* __restrict__ wb,
    float*       __restrict__ out)
{
    const int b   = blockIdx.x;
    const int tid = threadIdx.x;
    const bool is_q = (tid < 128);
    const int  p    = is_q ? 0 : 1;
    const int  tp   = tid & 127;
    const bool top  = (tp < 64);

    __shared__ __align__(16) float sx[2][2][PQ];       // [panel][buf][8x24 row-major]
    __shared__ __align__(16) float sC[2][8 * CPAD];    // panels, column-major padded
    __shared__ __align__(16) float sE[2][8 * CPAD];
    __shared__ __align__(16) float sD[2][8 * CPAD];
    __shared__ int   stok[2][TSEQ];
    // epilogue scratch
    __shared__ __align__(16) float syb[N_DIM * CPAD];  // yb row-major padded
    __shared__ __align__(16) float sUq[N_DIM * RPAD];  // rotated Q panel, row-major
    __shared__ __align__(16) float sCa[N_DIM * RPAD];  // A panel, row-major
    __shared__ float sA8[8 * 16];
    __shared__ float sW8[PQ];
    __shared__ float sbias[PQ];
    __shared__ float red[8];

    const float* emb  = is_q ? emb_q : emb_a;
    const int*   sent = is_q ? s1    : s2;

    // transforms cached in regs (answer panel: identity)
    float tf1 = 1.0f, tf2 = 1.0f;
    if (is_q) {
        tf1 = transforms[tp];
        if (top) tf2 = transforms[tp + 128];
    }

    // tokens
    if (top) stok[p][tp] = sent[b * TSEQ + tp];

    float* sCp = sC[p];
    float* sEp = sE[p];
    float* sDp = sD[p];

    // geometry
    const int c  = tp & 7;
    const int r  = tp >> 3;              // top only (0..7)
    const int jg = (tp - 64) >> 3;       // bottom only (0..7)
    const int j0 = 3 * jg;

    // init C = [I8; 0]
    if (top) {
        sCp[c * CPAD + r] = (r == c) ? 1.0f : 0.0f;
    } else {
        sCp[c * CPAD + 8 + j0 + 0] = 0.0f;
        sCp[c * CPAD + 8 + j0 + 1] = 0.0f;
        sCp[c * CPAD + 8 + j0 + 2] = 0.0f;
    }
    __syncthreads();

    // first x (t = 63) into buffer 1
    {
        int tok = stok[p][TSEQ - 1];
        sx[p][1][tp] = emb[(size_t)tok * PQ + tp] * tf1;
        if (top) sx[p][1][tp + 128] = emb[(size_t)tok * PQ + tp + 128] * tf2;
    }
    __syncthreads();

    float rx[24];

    #pragma unroll 1
    for (int t = TSEQ - 1; t >= 0; --t) {
        const float* xb = sx[p][t & 1];

        // prefetch next token's embedding row (L2-resident after warmup)
        float xn1 = 0.0f, xn2 = 0.0f;
        if (t > 0) {
            int tok = stok[p][t - 1];
            xn1 = emb[(size_t)tok * PQ + tp];
            if (top) xn2 = emb[(size_t)tok * PQ + tp + 128];
        }

        // cache x slice in registers
        if (top) {
            const float4* px = (const float4*)(xb + r * Q_DIM);
            #pragma unroll
            for (int m = 0; m < 6; ++m) {
                float4 v = px[m];
                rx[4*m] = v.x; rx[4*m+1] = v.y; rx[4*m+2] = v.z; rx[4*m+3] = v.w;
            }
        } else {
            #pragma unroll
            for (int i = 0; i < 8; ++i) {
                rx[i*3 + 0] = xb[i * Q_DIM + j0 + 0];
                rx[i*3 + 1] = xb[i * Q_DIM + j0 + 1];
                rx[i*3 + 2] = xb[i * Q_DIM + j0 + 2];
            }
        }

        // ---- Phase 1: E = XC - C
        if (top) {
            const float4* pc = (const float4*)(&sCp[c * CPAD + 8]);
            float a0 = 0.f, a1 = 0.f, a2 = 0.f, a3 = 0.f;
            #pragma unroll
            for (int m = 0; m < 6; ++m) {
                float4 v = pc[m];
                a0 += rx[4*m] * v.x;  a1 += rx[4*m+1] * v.y;
                a2 += rx[4*m+2] * v.z; a3 += rx[4*m+3] * v.w;
            }
            sEp[c * CPAD + r] = (a0 + a1) + (a2 + a3) - sCp[c * CPAD + r];
        } else {
            const float4* pc = (const float4*)(&sCp[c * CPAD]);
            float4 v0 = pc[0], v1 = pc[1];
            #pragma unroll
            for (int d = 0; d < 3; ++d) {
                float acc = rx[0+d]*v0.x + rx[3+d]*v0.y + rx[6+d]*v0.z + rx[9+d]*v0.w
                          + rx[12+d]*v1.x + rx[15+d]*v1.y + rx[18+d]*v1.z + rx[21+d]*v1.w;
                sEp[c * CPAD + 8 + j0 + d] = -sCp[c * CPAD + 8 + j0 + d] - acc;
            }
        }
        __syncthreads();

        // ---- Phase 2: D = XE + C
        if (top) {
            const float4* pe = (const float4*)(&sEp[c * CPAD + 8]);
            float a0 = 0.f, a1 = 0.f, a2 = 0.f, a3 = 0.f;
            #pragma unroll
            for (int m = 0; m < 6; ++m) {
                float4 v = pe[m];
                a0 += rx[4*m] * v.x;  a1 += rx[4*m+1] * v.y;
                a2 += rx[4*m+2] * v.z; a3 += rx[4*m+3] * v.w;
            }
            sDp[c * CPAD + r] = (a0 + a1) + (a2 + a3) + sCp[c * CPAD + r];
        } else {
            const float4* pe = (const float4*)(&sEp[c * CPAD]);
            float4 v0 = pe[0], v1 = pe[1];
            #pragma unroll
            for (int d = 0; d < 3; ++d) {
                float acc = rx[0+d]*v0.x + rx[3+d]*v0.y + rx[6+d]*v0.z + rx[9+d]*v0.w
                          + rx[12+d]*v1.x + rx[15+d]*v1.y + rx[18+d]*v1.z + rx[21+d]*v1.w;
                sDp[c * CPAD + 8 + j0 + d] = sCp[c * CPAD + 8 + j0 + d] - acc;
            }
        }
        __syncthreads();

        // ---- Phase 3: C' = C - 2XD  (in place; each thread touches only its own C)
        if (top) {
            const float4* pd = (const float4*)(&sDp[c * CPAD + 8]);
            float a0 = 0.f, a1 = 0.f, a2 = 0.f, a3 = 0.f;
            #pragma unroll
            for (int m = 0; m < 6; ++m) {
                float4 v = pd[m];
                a0 += rx[4*m] * v.x;  a1 += rx[4*m+1] * v.y;
                a2 += rx[4*m+2] * v.z; a3 += rx[4*m+3] * v.w;
            }
            sCp[c * CPAD + r] -= 2.0f * ((a0 + a1) + (a2 + a3));
        } else {
            const float4* pd = (const float4*)(&sDp[c * CPAD]);
            float4 v0 = pd[0], v1 = pd[1];
            #pragma unroll
            for (int d = 0; d < 3; ++d) {
                float acc = rx[0+d]*v0.x + rx[3+d]*v0.y + rx[6+d]*v0.z + rx[9+d]*v0.w
                          + rx[12+d]*v1.x + rx[15+d]*v1.y + rx[18+d]*v1.z + rx[21+d]*v1.w;
                sCp[c * CPAD + 8 + j0 + d] += 2.0f * acc;
            }
        }

        // commit next x into the other buffer (readers consume after the barrier)
        if (t > 0) {
            float* xo = sx[p][(t & 1) ^ 1];
            xo[tp] = xn1 * tf1;
            if (top) xo[tp + 128] = xn2 * tf2;
        }
        __syncthreads();
    }

    // =====================  EPILOGUE  =====================
    // 1) yb = cayley(tangent(bias)) via exact 8x8 Gauss-Jordan (all blocks, redundant)
    if (tid < PQ) sbias[tid] = bias[tid];
    __syncthreads();

    if (tid < 128) {
        int i = tid >> 4, cc = tid & 15;
        float v;
        if (cc < 8) {
            v = (i == cc) ? 1.0f : 0.0f;
            #pragma unroll
            for (int k = 0; k < Q_DIM; ++k) v += sbias[i * Q_DIM + k] * sbias[cc * Q_DIM + k];
        } else {
            v = (i == cc - 8) ? 1.0f : 0.0f;
        }
        sA8[i * 16 + cc] = v;
    }
    __syncthreads();

    for (int k = 0; k < 8; ++k) {
        float nv = 0.0f;
        int i = tid >> 4, cc = tid & 15;
        if (tid < 128) {
            float piv = 1.0f / sA8[k * 16 + k];
            float akc = sA8[k * 16 + cc] * piv;
            nv = (i == k) ? akc : (sA8[i * 16 + cc] - sA8[i * 16 + k] * akc);
        }
        __syncthreads();
        if (tid < 128) sA8[i * 16 + cc] = nv;
        __syncthreads();
    }

    if (tid < PQ) {
        int i = tid / Q_DIM, jj = tid % Q_DIM;
        float w = 0.0f;
        #pragma unroll
        for (int k = 0; k < 8; ++k) w += sA8[i * 16 + 8 + k] * sbias[k * Q_DIM + jj];
        sW8[tid] = w;
    }
    __syncthreads();

    #pragma unroll
    for (int e = 0; e < 4; ++e) {
        int idx = tid + 256 * e;
        int rr = idx >> 5, cc = idx & 31;
        float y;
        if (rr < 8 && cc < 8) {
            y = 2.0f * sA8[rr * 16 + 8 + cc] - ((rr == cc) ? 1.0f : 0.0f);
        } else if (rr < 8) {
            y = -2.0f * sW8[rr * Q_DIM + (cc - 8)];
        } else if (cc < 8) {
            y = 2.0f * sW8[cc * Q_DIM + (rr - 8)];
        } else {
            int jj = rr - 8, c2 = cc - 8;
            float acc = 0.0f;
            #pragma unroll
            for (int i = 0; i < 8; ++i) acc += sbias[i * Q_DIM + jj] * sW8[i * Q_DIM + c2];
            y = ((jj == c2) ? 1.0f : 0.0f) - 2.0f * acc;
        }
        syb[rr * CPAD + cc] = y;
    }
    __syncthreads();

    // 2) U_q = yb * C_q (row-major), C_a transposed to row-major
    {
        int rr = tid >> 3, cc = tid & 7;
        const float4* yr = (const float4*)(&syb[rr * CPAD]);
        const float4* cq = (const float4*)(&sC[0][cc * CPAD]);
        float a0 = 0.f, a1 = 0.f, a2 = 0.f, a3 = 0.f;
        #pragma unroll
        for (int m = 0; m < 8; ++m) {
            float4 yv = yr[m];
            float4 cv = cq[m];
            a0 += yv.x * cv.x; a1 += yv.y * cv.y; a2 += yv.z * cv.z; a3 += yv.w * cv.w;
        }
        sUq[rr * RPAD + cc] = (a0 + a1) + (a2 + a3);
        sCa[rr * RPAD + cc] = sC[1][cc * CPAD + rr];
    }
    __syncthreads();

    // 3) dist^2 = sum_{i,jj} ( (Uq Uq^T)_{i,jj} - (Ca Ca^T)_{i,jj} )^2
    float acc = 0.0f;
    #pragma unroll
    for (int e = 0; e < 4; ++e) {
        int idx = tid + 256 * e;
        int i = idx >> 5, jj = idx & 31;
        const float4* ui = (const float4*)(&sUq[i  * RPAD]);
        const float4* uj = (const float4*)(&sUq[jj * RPAD]);
        const float4* ai = (const float4*)(&sCa[i  * RPAD]);
        const float4* aj = (const float4*)(&sCa[jj * RPAD]);
        float d = 0.0f;
        #pragma unroll
        for (int m = 0; m < 2; ++m) {
            float4 a = ui[m], bq = uj[m], x = ai[m], y = aj[m];
            d += a.x * bq.x + a.y * bq.y + a.z * bq.z + a.w * bq.w;
            d -= x.x * y.x  + x.y * y.y  + x.z * y.z  + x.w * y.w;
        }
        acc += d * d;
    }

    #pragma unroll
    for (int off = 16; off > 0; off >>= 1)
        acc += __shfl_xor_sync(0xFFFFFFFFu, acc, off);
    if ((tid & 31) == 0) red[tid >> 5] = acc;
    __syncthreads();
    if (tid == 0) {
        float s = 0.0f;
        #pragma unroll
        for (int w = 0; w < 8; ++w) s += red[w];
        out[b] = -(*wf) * sqrtf(s) + (*wb);
    }
}

// ---------------------------------------------------------------------------
extern "C" void kernel_launch(void* const* d_in, const int* in_sizes, int n_in,
                              void* d_out, int out_size)
{
    const int*   s1 = (const int*)  d_in[0];   // sentence_1 [512,64]
    const int*   s2 = (const int*)  d_in[1];   // sentence_2 [512,64]
    const float* qe = (const float*)d_in[2];   // question_embedding [32000,8,24]
    const float* ae = (const float*)d_in[3];   // answer_embedding   [32000,8,24]
    const float* qt = (const float*)d_in[4];   // question_transforms [8,24]
    const float* qb = (const float*)d_in[5];   // question_bias [8,24]
    const float* wf = (const float*)d_in[6];
    const float* wb = (const float*)d_in[7];
    float* out = (float*)d_out;

    fused_kernel<<<BATCH, 256>>>(s1, s2, qe, ae, qt, qb, wf, wb, out);
}